// round 16
// baseline (speedup 1.0000x reference)
#include <cuda_runtime.h>

// ---------------------------------------------------------------------------
// DyNet2D R15: Winograd F(4x4,3x3). R13 base (best: 565us) + phase-C warp
// remix: tid = tile*8 + ocpair -> warp = 4 tiles x 8 oc-pairs.
//   u loads:  8 distinct addrs x16B = 1 wf (was 2)
//   bd load:  4 distinct addrs      = 1 wf
// -> phase-C wavefronts 9216 -> 6912 per SM-round, same instrs/FMAs/accs.
// ---------------------------------------------------------------------------

#define HW (512 * 512)

__device__ float g_partial[1024];                       // (b*16+c)*4 + quarter
__device__ __align__(16) float g_u[16 * 16 * 9 * 64];   // [b][ic][q][oc][4]

// ------------------------------ 1) pooling --------------------------------
__global__ void pool_kernel(const float* __restrict__ x) {
    const int blk = blockIdx.x;
    const int bc  = blk >> 2;
    const int q   = blk & 3;
    const float4* p = reinterpret_cast<const float4*>(x + (size_t)bc * HW + (size_t)q * 65536);
    float s = 0.0f;
    #pragma unroll 4
    for (int i = threadIdx.x; i < 16384; i += 256) {
        float4 v = p[i];
        s += (v.x + v.y) + (v.z + v.w);
    }
    #pragma unroll
    for (int o = 16; o > 0; o >>= 1) s += __shfl_down_sync(0xffffffffu, s, o);
    __shared__ float ws[8];
    if ((threadIdx.x & 31) == 0) ws[threadIdx.x >> 5] = s;
    __syncthreads();
    if (threadIdx.x == 0) {
        float t = 0.0f;
        #pragma unroll
        for (int i = 0; i < 8; i++) t += ws[i];
        g_partial[blk] = t;
    }
}

// --------------- 2) routing softmax + Winograd weight transform -----------
__global__ void mix_kernel(const float* __restrict__ w_experts,
                           const float* __restrict__ fc_w,
                           const float* __restrict__ fc_b) {
    __shared__ float pooled_s[256];
    __shared__ float r_s[16][3];
    const int tid = threadIdx.x;

    pooled_s[tid] = (g_partial[tid * 4 + 0] + g_partial[tid * 4 + 1] +
                     g_partial[tid * 4 + 2] + g_partial[tid * 4 + 3]) * (1.0f / (float)HW);
    __syncthreads();

    if (tid < 16) {
        float lg[3];
        #pragma unroll
        for (int e = 0; e < 3; e++) {
            float a = fc_b[e];
            #pragma unroll
            for (int c = 0; c < 16; c++) a += pooled_s[tid * 16 + c] * fc_w[e * 16 + c];
            lg[e] = a;
        }
        float m = fmaxf(lg[0], fmaxf(lg[1], lg[2]));
        float ex0 = expf(lg[0] - m), ex1 = expf(lg[1] - m), ex2 = expf(lg[2] - m);
        float inv = 1.0f / (ex0 + ex1 + ex2);
        r_s[tid][0] = ex0 * inv;
        r_s[tid][1] = ex1 * inv;
        r_s[tid][2] = ex2 * inv;
    }
    __syncthreads();

    for (int job = tid; job < 4096; job += 256) {
        int b  = job >> 8;
        int ic = (job >> 4) & 15;
        int oc = job & 15;

        float w[3][3];
        #pragma unroll
        for (int r = 0; r < 3; r++)
            #pragma unroll
            for (int c = 0; c < 3; c++) {
                float v = 0.0f;
                #pragma unroll
                for (int e = 0; e < 3; e++)
                    v += r_s[b][e] * w_experts[((e * 16 + oc) * 16 + ic) * 9 + r * 3 + c];
                w[r][c] = v;
            }

        float T[6][3];
        #pragma unroll
        for (int c = 0; c < 3; c++) {
            float w0 = w[0][c], w1 = w[1][c], w2 = w[2][c];
            T[0][c] = 0.25f * w0;
            T[1][c] = (-1.0f / 6.0f) * (w0 + w1 + w2);
            T[2][c] = (1.0f / 6.0f) * (-w0 + w1 - w2);
            T[3][c] = (1.0f / 24.0f) * w0 + (1.0f / 12.0f) * w1 + (1.0f / 6.0f) * w2;
            T[4][c] = (1.0f / 24.0f) * w0 - (1.0f / 12.0f) * w1 + (1.0f / 6.0f) * w2;
            T[5][c] = w2;
        }
        float u36[36];
        #pragma unroll
        for (int i = 0; i < 6; i++) {
            float t0 = T[i][0], t1 = T[i][1], t2 = T[i][2];
            u36[i * 6 + 0] = 0.25f * t0;
            u36[i * 6 + 1] = (-1.0f / 6.0f) * (t0 + t1 + t2);
            u36[i * 6 + 2] = (1.0f / 6.0f) * (-t0 + t1 - t2);
            u36[i * 6 + 3] = (1.0f / 24.0f) * t0 + (1.0f / 12.0f) * t1 + (1.0f / 6.0f) * t2;
            u36[i * 6 + 4] = (1.0f / 24.0f) * t0 - (1.0f / 12.0f) * t1 + (1.0f / 6.0f) * t2;
            u36[i * 6 + 5] = t2;
        }
        float* base = g_u + (size_t)(b * 16 + ic) * 576 + oc * 4;
        #pragma unroll
        for (int q = 0; q < 9; q++) {
            base[q * 64 + 0] = u36[q * 4 + 0];
            base[q * 64 + 1] = u36[q * 4 + 1];
            base[q * 64 + 2] = u36[q * 4 + 2];
            base[q * 64 + 3] = u36[q * 4 + 3];
        }
    }
}

// ------- no-op: shifts ncu's -s 5 capture slot onto conv_kernel -----------
__global__ void tag_kernel() {}

// ------------------------- 3) Winograd conv -------------------------------
__device__ __forceinline__ void btrans(float v0, float v1, float v2, float v3,
                                       float v4, float v5,
                                       float& o0, float& o1, float& o2,
                                       float& o3, float& o4, float& o5) {
    float a = v1 + v2;
    float b = v3 + v4;
    float c = v1 - v2;
    float e = v4 - v3;
    float f = v3 - v1;
    float g = v4 - v2;
    o0 = fmaf(4.0f, v0, fmaf(-5.0f, v2, v4));
    o1 = fmaf(-4.0f, a, b);
    o2 = fmaf(4.0f, c, e);
    o3 = fmaf(2.0f, f, g);
    o4 = fmaf(-2.0f, f, g);
    o5 = fmaf(4.0f, v1, fmaf(-5.0f, v3, v5));
}

__device__ __forceinline__ void atrans(float v0, float v1, float v2, float v3,
                                       float v4, float v5,
                                       float& o0, float& o1, float& o2, float& o3) {
    float s1 = v1 + v2;
    float s2 = v1 - v2;
    float s3 = v3 + v4;
    float s4 = v3 - v4;
    o0 = v0 + s1 + s3;
    o1 = fmaf(2.0f, s4, s2);
    o2 = fmaf(4.0f, s3, s1);
    o3 = fmaf(8.0f, s4, s2) + v5;
}

// SMEM (floats):
//   bd_s  : [16 ic][9 q][32 tile][4] -> 18432  (offset 0)
//   union : 10368                      (offset 18432)
//       phases A/B: in_s [16 ic][18 rows][36 stride] (cols 0..33 used)
//       phase  C  : w_s  [16 ic][9 q][16 oc][4] = 9216
// total 28800 floats = 115200 bytes -> 2 CTAs/SM
__global__ void __launch_bounds__(256, 2)
conv_kernel(const float* __restrict__ x, const float* __restrict__ bias,
            float* __restrict__ out) {
    extern __shared__ float smem[];
    float* bd_s = smem;
    float* un_s = smem + 18432;      // in_s during A/B, w_s during C

    const int tid = threadIdx.x;
    const int b   = blockIdx.z;
    const int x0  = blockIdx.x * 32;
    const int y0  = blockIdx.y * 16;

    // phase C/D mapping: tile-major, oc-pair per thread
    const int pcp  = tid & 7;        // oc pair: oc = 2*pcp, 2*pcp+1
    const int tile = tid >> 3;       // 0..31

    const float bv0 = bias[2 * pcp];
    const float bv1 = bias[2 * pcp + 1];
    const float* xb = x + (size_t)b * 16 * HW;

    // ---- phase A: input tile 16ic x 18 x 34 (reflect halo), stride 36 ----
    for (int i = tid; i < 9792; i += 256) {
        int c   = i / 612;                   // 18*34
        int rem = i - c * 612;
        int row = rem / 34;
        int col = rem - row * 34;
        int gy = y0 + row - 1; gy = gy < 0 ? -gy : (gy > 511 ? 1022 - gy : gy);
        int gx = x0 + col - 1; gx = gx < 0 ? -gx : (gx > 511 ? 1022 - gx : gx);
        un_s[c * 648 + row * 36 + col] = xb[(c << 18) + (gy << 9) + gx];
    }
    __syncthreads();

    // ---- phase B: vectorized two-stage input transform, 2 jobs/thread ----
    #pragma unroll 1
    for (int s = 0; s < 2; s++) {
        const int job  = tid + s * 256;
        const int b_ic = job >> 5;
        const int b_t  = job & 31;
        const int b_tx = b_t & 7;
        const int b_ty = b_t >> 3;
        const float* p = un_s + b_ic * 648 + (4 * b_ty) * 36 + 4 * b_tx;

        float rowt[6][6];
        #pragma unroll
        for (int r = 0; r < 6; r++) {
            float4 a  = *reinterpret_cast<const float4*>(p + r * 36);
            float2 b2 = *reinterpret_cast<const float2*>(p + r * 36 + 4);
            btrans(a.x, a.y, a.z, a.w, b2.x, b2.y,
                   rowt[r][0], rowt[r][1], rowt[r][2],
                   rowt[r][3], rowt[r][4], rowt[r][5]);
        }
        float bd[36];
        #pragma unroll
        for (int j = 0; j < 6; j++)
            btrans(rowt[0][j], rowt[1][j], rowt[2][j],
                   rowt[3][j], rowt[4][j], rowt[5][j],
                   bd[0 + j], bd[6 + j], bd[12 + j],
                   bd[18 + j], bd[24 + j], bd[30 + j]);

        float* dst = bd_s + b_ic * 1152 + b_t * 4;
        #pragma unroll
        for (int q = 0; q < 9; q++)
            *reinterpret_cast<float4*>(dst + q * 128) =
                make_float4(bd[q * 4 + 0], bd[q * 4 + 1], bd[q * 4 + 2], bd[q * 4 + 3]);
    }
    __syncthreads();

    // ---- load transformed weights into union (in_s dead now) ----
    {
        const float4* src = reinterpret_cast<const float4*>(g_u + (size_t)b * 9216);
        float4* dst = reinterpret_cast<float4*>(un_s);
        #pragma unroll
        for (int k = 0; k < 9; k++) {
            int i = tid + k * 256;
            if (i < 2304) dst[i] = src[i];
        }
    }
    __syncthreads();

    // ---- phase C: ic outer, q fully unrolled; 1 tile x 2 oc per thread ----
    float m0[36], m1[36];
    #pragma unroll
    for (int j = 0; j < 36; j++) { m0[j] = 0.0f; m1[j] = 0.0f; }
    {
        const float* wq  = un_s + pcp * 8;      // + ic*576 + q*64 ; u1 = +4
        const float* bdq = bd_s + tile * 4;     // + ic*1152 + q*128
        #pragma unroll 1
        for (int ic = 0; ic < 16; ic++) {
            #pragma unroll
            for (int q = 0; q < 9; q++) {
                float4 bq = *reinterpret_cast<const float4*>(bdq + q * 128);
                float4 u0 = *reinterpret_cast<const float4*>(wq  + q * 64);
                float4 u1 = *reinterpret_cast<const float4*>(wq  + q * 64 + 4);
                m0[q*4+0] = fmaf(bq.x, u0.x, m0[q*4+0]);
                m0[q*4+1] = fmaf(bq.y, u0.y, m0[q*4+1]);
                m0[q*4+2] = fmaf(bq.z, u0.z, m0[q*4+2]);
                m0[q*4+3] = fmaf(bq.w, u0.w, m0[q*4+3]);
                m1[q*4+0] = fmaf(bq.x, u1.x, m1[q*4+0]);
                m1[q*4+1] = fmaf(bq.y, u1.y, m1[q*4+1]);
                m1[q*4+2] = fmaf(bq.z, u1.z, m1[q*4+2]);
                m1[q*4+3] = fmaf(bq.w, u1.w, m1[q*4+3]);
            }
            wq  += 576;
            bdq += 1152;
        }
    }

    // ---- phase D: A^T m A + bias, same tile, both oc ----
    const int tx = tile & 7;
    const int ty = tile >> 3;
    #pragma unroll
    for (int h = 0; h < 2; h++) {
        const float* m = h ? m1 : m0;
        const float bv = h ? bv1 : bv0;
        const int oc = 2 * pcp + h;

        float t[4][6];
        #pragma unroll
        for (int j = 0; j < 6; j++)
            atrans(m[0 * 6 + j], m[1 * 6 + j], m[2 * 6 + j],
                   m[3 * 6 + j], m[4 * 6 + j], m[5 * 6 + j],
                   t[0][j], t[1][j], t[2][j], t[3][j]);

        float* op = out + ((size_t)(b * 16 + oc) << 18) +
                    ((size_t)(y0 + 4 * ty) << 9) + (x0 + 4 * tx);
        #pragma unroll
        for (int r = 0; r < 4; r++) {
            float o0, o1, o2, o3;
            atrans(t[r][0], t[r][1], t[r][2], t[r][3], t[r][4], t[r][5],
                   o0, o1, o2, o3);
            *reinterpret_cast<float4*>(op + ((size_t)r << 9)) =
                make_float4(o0 + bv, o1 + bv, o2 + bv, o3 + bv);
        }
    }
}

// ---------------------------------------------------------------------------
extern "C" void kernel_launch(void* const* d_in, const int* in_sizes, int n_in,
                              void* d_out, int out_size) {
    const float* x         = (const float*)d_in[0];
    const float* w_experts = (const float*)d_in[1];
    const float* bias      = (const float*)d_in[2];
    const float* fc_w      = (const float*)d_in[3];
    const float* fc_b      = (const float*)d_in[4];
    float* out = (float*)d_out;

    const int smem_bytes = 28800 * 4;   // 115200
    cudaFuncSetAttribute(conv_kernel, cudaFuncAttributeMaxDynamicSharedMemorySize, smem_bytes);

    pool_kernel<<<1024, 256>>>(x);
    mix_kernel<<<1, 256>>>(w_experts, fc_w, fc_b);
    tag_kernel<<<1, 32>>>();
    conv_kernel<<<dim3(16, 32, 16), 256, smem_bytes>>>(x, bias, out);
}

// round 17
// speedup vs baseline: 1.4395x; 1.4395x over previous
#include <cuda_runtime.h>

// ---------------------------------------------------------------------------
// DyNet2D R16: Winograd F(4x4,3x3). R13 base + phase-C row-pair blocking:
// 3 blocks of 3 quads; after each block the 2 finished M-rows fold into the
// column-transform accumulators t[4][6] (A^T is linear) freeing their regs.
// Live set: t 48 + block-m 24 + 36 operands ~= 120 < 128 -> no spills,
// with T=2 u/bd amortization fully preserved (loads identical to R13).
// ---------------------------------------------------------------------------

#define HW (512 * 512)

__device__ float g_partial[1024];                       // (b*16+c)*4 + quarter
__device__ __align__(16) float g_u[16 * 16 * 9 * 64];   // [b][ic][q][oc][4]

// ------------------------------ 1) pooling --------------------------------
__global__ void pool_kernel(const float* __restrict__ x) {
    const int blk = blockIdx.x;
    const int bc  = blk >> 2;
    const int q   = blk & 3;
    const float4* p = reinterpret_cast<const float4*>(x + (size_t)bc * HW + (size_t)q * 65536);
    float s = 0.0f;
    #pragma unroll 4
    for (int i = threadIdx.x; i < 16384; i += 256) {
        float4 v = p[i];
        s += (v.x + v.y) + (v.z + v.w);
    }
    #pragma unroll
    for (int o = 16; o > 0; o >>= 1) s += __shfl_down_sync(0xffffffffu, s, o);
    __shared__ float ws[8];
    if ((threadIdx.x & 31) == 0) ws[threadIdx.x >> 5] = s;
    __syncthreads();
    if (threadIdx.x == 0) {
        float t = 0.0f;
        #pragma unroll
        for (int i = 0; i < 8; i++) t += ws[i];
        g_partial[blk] = t;
    }
}

// --------------- 2) routing softmax + Winograd weight transform -----------
__global__ void mix_kernel(const float* __restrict__ w_experts,
                           const float* __restrict__ fc_w,
                           const float* __restrict__ fc_b) {
    __shared__ float pooled_s[256];
    __shared__ float r_s[16][3];
    const int tid = threadIdx.x;

    pooled_s[tid] = (g_partial[tid * 4 + 0] + g_partial[tid * 4 + 1] +
                     g_partial[tid * 4 + 2] + g_partial[tid * 4 + 3]) * (1.0f / (float)HW);
    __syncthreads();

    if (tid < 16) {
        float lg[3];
        #pragma unroll
        for (int e = 0; e < 3; e++) {
            float a = fc_b[e];
            #pragma unroll
            for (int c = 0; c < 16; c++) a += pooled_s[tid * 16 + c] * fc_w[e * 16 + c];
            lg[e] = a;
        }
        float m = fmaxf(lg[0], fmaxf(lg[1], lg[2]));
        float ex0 = expf(lg[0] - m), ex1 = expf(lg[1] - m), ex2 = expf(lg[2] - m);
        float inv = 1.0f / (ex0 + ex1 + ex2);
        r_s[tid][0] = ex0 * inv;
        r_s[tid][1] = ex1 * inv;
        r_s[tid][2] = ex2 * inv;
    }
    __syncthreads();

    for (int job = tid; job < 4096; job += 256) {
        int b  = job >> 8;
        int ic = (job >> 4) & 15;
        int oc = job & 15;

        float w[3][3];
        #pragma unroll
        for (int r = 0; r < 3; r++)
            #pragma unroll
            for (int c = 0; c < 3; c++) {
                float v = 0.0f;
                #pragma unroll
                for (int e = 0; e < 3; e++)
                    v += r_s[b][e] * w_experts[((e * 16 + oc) * 16 + ic) * 9 + r * 3 + c];
                w[r][c] = v;
            }

        float T[6][3];
        #pragma unroll
        for (int c = 0; c < 3; c++) {
            float w0 = w[0][c], w1 = w[1][c], w2 = w[2][c];
            T[0][c] = 0.25f * w0;
            T[1][c] = (-1.0f / 6.0f) * (w0 + w1 + w2);
            T[2][c] = (1.0f / 6.0f) * (-w0 + w1 - w2);
            T[3][c] = (1.0f / 24.0f) * w0 + (1.0f / 12.0f) * w1 + (1.0f / 6.0f) * w2;
            T[4][c] = (1.0f / 24.0f) * w0 - (1.0f / 12.0f) * w1 + (1.0f / 6.0f) * w2;
            T[5][c] = w2;
        }
        float u36[36];
        #pragma unroll
        for (int i = 0; i < 6; i++) {
            float t0 = T[i][0], t1 = T[i][1], t2 = T[i][2];
            u36[i * 6 + 0] = 0.25f * t0;
            u36[i * 6 + 1] = (-1.0f / 6.0f) * (t0 + t1 + t2);
            u36[i * 6 + 2] = (1.0f / 6.0f) * (-t0 + t1 - t2);
            u36[i * 6 + 3] = (1.0f / 24.0f) * t0 + (1.0f / 12.0f) * t1 + (1.0f / 6.0f) * t2;
            u36[i * 6 + 4] = (1.0f / 24.0f) * t0 - (1.0f / 12.0f) * t1 + (1.0f / 6.0f) * t2;
            u36[i * 6 + 5] = t2;
        }
        float* base = g_u + (size_t)(b * 16 + ic) * 576 + oc * 4;
        #pragma unroll
        for (int q = 0; q < 9; q++) {
            base[q * 64 + 0] = u36[q * 4 + 0];
            base[q * 64 + 1] = u36[q * 4 + 1];
            base[q * 64 + 2] = u36[q * 4 + 2];
            base[q * 64 + 3] = u36[q * 4 + 3];
        }
    }
}

// ------- no-op: shifts ncu's -s 5 capture slot onto conv_kernel -----------
__global__ void tag_kernel() {}

// ------------------------- 3) Winograd conv -------------------------------
__device__ __forceinline__ void btrans(float v0, float v1, float v2, float v3,
                                       float v4, float v5,
                                       float& o0, float& o1, float& o2,
                                       float& o3, float& o4, float& o5) {
    float a = v1 + v2;
    float b = v3 + v4;
    float c = v1 - v2;
    float e = v4 - v3;
    float f = v3 - v1;
    float g = v4 - v2;
    o0 = fmaf(4.0f, v0, fmaf(-5.0f, v2, v4));
    o1 = fmaf(-4.0f, a, b);
    o2 = fmaf(4.0f, c, e);
    o3 = fmaf(2.0f, f, g);
    o4 = fmaf(-2.0f, f, g);
    o5 = fmaf(4.0f, v1, fmaf(-5.0f, v3, v5));
}

__device__ __forceinline__ void atrans(float v0, float v1, float v2, float v3,
                                       float v4, float v5,
                                       float& o0, float& o1, float& o2, float& o3) {
    float s1 = v1 + v2;
    float s2 = v1 - v2;
    float s3 = v3 + v4;
    float s4 = v3 - v4;
    o0 = v0 + s1 + s3;
    o1 = fmaf(2.0f, s4, s2);
    o2 = fmaf(4.0f, s3, s1);
    o3 = fmaf(8.0f, s4, s2) + v5;
}

// SMEM (floats):
//   bd_s  : [16 ic][9 q][32 tile][4] -> 18432  (offset 0)
//   union : 10368                      (offset 18432)
//       phases A/B: in_s [16 ic][18 rows][36 stride] (cols 0..33 used)
//       phase  C  : w_s  [16 ic][9 q][16 oc][4] = 9216
// total 28800 floats = 115200 bytes -> 2 CTAs/SM
__global__ void __launch_bounds__(256, 2)
conv_kernel(const float* __restrict__ x, const float* __restrict__ bias,
            float* __restrict__ out) {
    extern __shared__ float smem[];
    float* bd_s = smem;
    float* un_s = smem + 18432;      // in_s during A/B, w_s during C

    const int tid = threadIdx.x;
    const int b   = blockIdx.z;
    const int x0  = blockIdx.x * 32;
    const int y0  = blockIdx.y * 16;

    const int oc  = tid & 15;
    const int grp = tid >> 4;        // 0..15 -> tiles 2*grp, 2*grp+1

    const float bv = bias[oc];
    const float* xb = x + (size_t)b * 16 * HW;

    // ---- phase A: input tile 16ic x 18 x 34 (reflect halo), stride 36 ----
    for (int i = tid; i < 9792; i += 256) {
        int c   = i / 612;                   // 18*34
        int rem = i - c * 612;
        int row = rem / 34;
        int col = rem - row * 34;
        int gy = y0 + row - 1; gy = gy < 0 ? -gy : (gy > 511 ? 1022 - gy : gy);
        int gx = x0 + col - 1; gx = gx < 0 ? -gx : (gx > 511 ? 1022 - gx : gx);
        un_s[c * 648 + row * 36 + col] = xb[(c << 18) + (gy << 9) + gx];
    }
    __syncthreads();

    // ---- phase B: vectorized two-stage input transform, 2 jobs/thread ----
    #pragma unroll 1
    for (int s = 0; s < 2; s++) {
        const int job  = tid + s * 256;
        const int b_ic = job >> 5;
        const int b_t  = job & 31;
        const int b_tx = b_t & 7;
        const int b_ty = b_t >> 3;
        const float* p = un_s + b_ic * 648 + (4 * b_ty) * 36 + 4 * b_tx;

        float rowt[6][6];
        #pragma unroll
        for (int r = 0; r < 6; r++) {
            float4 a  = *reinterpret_cast<const float4*>(p + r * 36);
            float2 b2 = *reinterpret_cast<const float2*>(p + r * 36 + 4);
            btrans(a.x, a.y, a.z, a.w, b2.x, b2.y,
                   rowt[r][0], rowt[r][1], rowt[r][2],
                   rowt[r][3], rowt[r][4], rowt[r][5]);
        }
        float bd[36];
        #pragma unroll
        for (int j = 0; j < 6; j++)
            btrans(rowt[0][j], rowt[1][j], rowt[2][j],
                   rowt[3][j], rowt[4][j], rowt[5][j],
                   bd[0 + j], bd[6 + j], bd[12 + j],
                   bd[18 + j], bd[24 + j], bd[30 + j]);

        float* dst = bd_s + b_ic * 1152 + b_t * 4;
        #pragma unroll
        for (int q = 0; q < 9; q++)
            *reinterpret_cast<float4*>(dst + q * 128) =
                make_float4(bd[q * 4 + 0], bd[q * 4 + 1], bd[q * 4 + 2], bd[q * 4 + 3]);
    }
    __syncthreads();

    // ---- load transformed weights into union (in_s dead now) ----
    {
        const float4* src = reinterpret_cast<const float4*>(g_u + (size_t)b * 9216);
        float4* dst = reinterpret_cast<float4*>(un_s);
        #pragma unroll
        for (int k = 0; k < 9; k++) {
            int i = tid + k * 256;
            if (i < 2304) dst[i] = src[i];
        }
    }
    __syncthreads();

    // ---- phase C: 3 row-pair blocks of 3 quads; fold rows into t ----
    // t[r][j] accumulates AT*M incrementally (AT linear in M rows).
    float tA[4][6], tB[4][6];
    #pragma unroll
    for (int r = 0; r < 4; r++)
        #pragma unroll
        for (int j = 0; j < 6; j++) { tA[r][j] = 0.0f; tB[r][j] = 0.0f; }

    {
        const float* wq0  = un_s + oc * 4;      // + ic*576 + q*64
        const float* bdq0 = bd_s + grp * 8;     // + ic*1152 + q*128 (b1=+4)

        #pragma unroll
        for (int blk = 0; blk < 3; blk++) {
            // local m: rows 2*blk (ma/mb[0..5]) and 2*blk+1 (ma/mb[6..11])
            float ma[12], mb[12];
            #pragma unroll
            for (int j = 0; j < 12; j++) { ma[j] = 0.0f; mb[j] = 0.0f; }

            const float* wq  = wq0  + blk * 192;    // 3*64
            const float* bdq = bdq0 + blk * 384;    // 3*128
            #pragma unroll 1
            for (int ic = 0; ic < 16; ic++) {
                #pragma unroll
                for (int qq = 0; qq < 3; qq++) {
                    float4 u  = *reinterpret_cast<const float4*>(wq  + qq * 64);
                    float4 b0 = *reinterpret_cast<const float4*>(bdq + qq * 128);
                    float4 b1 = *reinterpret_cast<const float4*>(bdq + qq * 128 + 4);
                    ma[qq*4+0] = fmaf(b0.x, u.x, ma[qq*4+0]);
                    ma[qq*4+1] = fmaf(b0.y, u.y, ma[qq*4+1]);
                    ma[qq*4+2] = fmaf(b0.z, u.z, ma[qq*4+2]);
                    ma[qq*4+3] = fmaf(b0.w, u.w, ma[qq*4+3]);
                    mb[qq*4+0] = fmaf(b1.x, u.x, mb[qq*4+0]);
                    mb[qq*4+1] = fmaf(b1.y, u.y, mb[qq*4+1]);
                    mb[qq*4+2] = fmaf(b1.z, u.z, mb[qq*4+2]);
                    mb[qq*4+3] = fmaf(b1.w, u.w, mb[qq*4+3]);
                }
                wq  += 576;
                bdq += 1152;
            }

            // fold rows i0=2*blk, i1=2*blk+1 into t (AT coefficients)
            #pragma unroll
            for (int j = 0; j < 6; j++) {
                float a0 = ma[j], a1 = ma[6 + j];
                float c0 = mb[j], c1 = mb[6 + j];
                if (blk == 0) {
                    // i=0: [1,0,0,0]; i=1: [1,1,1,1]
                    tA[0][j] += a0 + a1; tA[1][j] += a1;
                    tA[2][j] += a1;      tA[3][j] += a1;
                    tB[0][j] += c0 + c1; tB[1][j] += c1;
                    tB[2][j] += c1;      tB[3][j] += c1;
                } else if (blk == 1) {
                    // i=2: [1,-1,1,-1]; i=3: [1,2,4,8]
                    tA[0][j] += a0 + a1;
                    tA[1][j] += fmaf(2.0f, a1, -a0);
                    tA[2][j] += fmaf(4.0f, a1,  a0);
                    tA[3][j] += fmaf(8.0f, a1, -a0);
                    tB[0][j] += c0 + c1;
                    tB[1][j] += fmaf(2.0f, c1, -c0);
                    tB[2][j] += fmaf(4.0f, c1,  c0);
                    tB[3][j] += fmaf(8.0f, c1, -c0);
                } else {
                    // i=4: [1,-2,4,-8]; i=5: [0,0,0,1]
                    tA[0][j] += a0;
                    tA[1][j] -= 2.0f * a0;
                    tA[2][j] += 4.0f * a0;
                    tA[3][j] += fmaf(-8.0f, a0, a1);
                    tB[0][j] += c0;
                    tB[1][j] -= 2.0f * c0;
                    tB[2][j] += 4.0f * c0;
                    tB[3][j] += fmaf(-8.0f, c0, c1);
                }
            }
        }
    }

    // ---- phase D: second-stage A^T (row transform) + bias, both tiles ----
    #pragma unroll
    for (int t2 = 0; t2 < 2; t2++) {
        const int tile = grp * 2 + t2;
        const int tx = tile & 7;
        const int ty = tile >> 3;

        float* op = out + ((size_t)(b * 16 + oc) << 18) +
                    ((size_t)(y0 + 4 * ty) << 9) + (x0 + 4 * tx);
        #pragma unroll
        for (int r = 0; r < 4; r++) {
            float v0 = t2 ? tB[r][0] : tA[r][0];
            float v1 = t2 ? tB[r][1] : tA[r][1];
            float v2 = t2 ? tB[r][2] : tA[r][2];
            float v3 = t2 ? tB[r][3] : tA[r][3];
            float v4 = t2 ? tB[r][4] : tA[r][4];
            float v5 = t2 ? tB[r][5] : tA[r][5];
            float o0, o1, o2, o3;
            atrans(v0, v1, v2, v3, v4, v5, o0, o1, o2, o3);
            *reinterpret_cast<float4*>(op + ((size_t)r << 9)) =
                make_float4(o0 + bv, o1 + bv, o2 + bv, o3 + bv);
        }
    }
}

// ---------------------------------------------------------------------------
extern "C" void kernel_launch(void* const* d_in, const int* in_sizes, int n_in,
                              void* d_out, int out_size) {
    const float* x         = (const float*)d_in[0];
    const float* w_experts = (const float*)d_in[1];
    const float* bias      = (const float*)d_in[2];
    const float* fc_w      = (const float*)d_in[3];
    const float* fc_b      = (const float*)d_in[4];
    float* out = (float*)d_out;

    const int smem_bytes = 28800 * 4;   // 115200
    cudaFuncSetAttribute(conv_kernel, cudaFuncAttributeMaxDynamicSharedMemorySize, smem_bytes);

    pool_kernel<<<1024, 256>>>(x);
    mix_kernel<<<1, 256>>>(w_experts, fc_w, fc_b);
    tag_kernel<<<1, 32>>>();
    conv_kernel<<<dim3(16, 32, 16), 256, smem_bytes>>>(x, bias, out);
}